// round 5
// baseline (speedup 1.0000x reference)
#include <cuda_runtime.h>

// Max pool 2x2 stride 2, NCHW (32,128,224,224) fp32 -> (32,128,112,112)
// HBM-bound streaming: 822MB read + 206MB write (mandatory).
//
// R5: 4 output quads per thread (16 independent float4 loads, 256B read/thread),
// 128-thread blocks, block covers 512 consecutive quads (grid 25088, no tail).
// Long read bursts then batched 4x STG.128 -> fewer DRAM read/write turnarounds.

#define IW  224
#define IH  224
#define OW  112
#define OH  112
#define OW4 28          // float4 quads per output row (112/4)
#define NC  (32 * 128)
#define TOTAL_QUADS (NC * OH * OW4)   // 12,845,056 = 512 * 25088

__device__ __forceinline__ void decode(int p, const float* __restrict__ in,
                                       const float4** r0, const float4** r1) {
    const int ow4 = p % OW4;
    const int t1  = p / OW4;
    const int oh  = t1 % OH;
    const int nc  = t1 / OH;
    const long long base = (long long)nc * (IH * IW) + (long long)(2 * oh) * IW + 8 * ow4;
    *r0 = reinterpret_cast<const float4*>(in + base);
    *r1 = reinterpret_cast<const float4*>(in + base + IW);
}

__device__ __forceinline__ float4 reduce2(float4 t0, float4 t1, float4 u0, float4 u1) {
    float4 r;
    r.x = fmaxf(fmaxf(t0.x, t0.y), fmaxf(u0.x, u0.y));
    r.y = fmaxf(fmaxf(t0.z, t0.w), fmaxf(u0.z, u0.w));
    r.z = fmaxf(fmaxf(t1.x, t1.y), fmaxf(u1.x, u1.y));
    r.w = fmaxf(fmaxf(t1.z, t1.w), fmaxf(u1.z, u1.w));
    return r;
}

__global__ __launch_bounds__(128, 6)
void pool2d_kernel(const float* __restrict__ in, float4* __restrict__ out) {
    // block covers 512 quads; thread t handles quads t, t+128, t+256, t+384
    const int p0 = blockIdx.x * 512 + threadIdx.x;
    const int p1 = p0 + 128;
    const int p2 = p0 + 256;
    const int p3 = p0 + 384;

    const float4 *a_r0, *a_r1, *b_r0, *b_r1, *c_r0, *c_r1, *d_r0, *d_r1;
    decode(p0, in, &a_r0, &a_r1);
    decode(p1, in, &b_r0, &b_r1);
    decode(p2, in, &c_r0, &c_r1);
    decode(p3, in, &d_r0, &d_r1);

    // 16 independent loads, front-batched
    const float4 a00 = __ldcs(a_r0);     const float4 a01 = __ldcs(a_r0 + 1);
    const float4 a10 = __ldcs(a_r1);     const float4 a11 = __ldcs(a_r1 + 1);
    const float4 b00 = __ldcs(b_r0);     const float4 b01 = __ldcs(b_r0 + 1);
    const float4 b10 = __ldcs(b_r1);     const float4 b11 = __ldcs(b_r1 + 1);
    const float4 c00 = __ldcs(c_r0);     const float4 c01 = __ldcs(c_r0 + 1);
    const float4 c10 = __ldcs(c_r1);     const float4 c11 = __ldcs(c_r1 + 1);
    const float4 d00 = __ldcs(d_r0);     const float4 d01 = __ldcs(d_r0 + 1);
    const float4 d10 = __ldcs(d_r1);     const float4 d11 = __ldcs(d_r1 + 1);

    const float4 r0 = reduce2(a00, a01, a10, a11);
    const float4 r1 = reduce2(b00, b01, b10, b11);
    const float4 r2 = reduce2(c00, c01, c10, c11);
    const float4 r3 = reduce2(d00, d01, d10, d11);

    __stcs(out + p0, r0);
    __stcs(out + p1, r1);
    __stcs(out + p2, r2);
    __stcs(out + p3, r3);
}

extern "C" void kernel_launch(void* const* d_in, const int* in_sizes, int n_in,
                              void* d_out, int out_size) {
    const float* x = (const float*)d_in[0];
    float4* out = (float4*)d_out;

    const int blocks  = TOTAL_QUADS / 512;   // 25088
    const int threads = 128;

    pool2d_kernel<<<blocks, threads>>>(x, out);
}